// round 10
// baseline (speedup 1.0000x reference)
#include <cuda_runtime.h>
#include <math.h>

#define MEM 2048
#define NV4 (MEM / 4)          // float4 per row = 512

// Scratch (allocation-free: __device__ globals)
__device__ float g_sL[MEM];    // w[j] * m_left[j]
__device__ float g_sR[MEM];    // w[j] * m_right[j]
__device__ float g_pL[MEM];    // (ma @ lh)[j]
__device__ float g_pR[MEM];    // (ma @ rh)[j]
__device__ float g_la[MEM];
__device__ float g_ra[MEM];
__device__ unsigned int g_count = 0;   // last-block detector (self-resetting)

__device__ __forceinline__ float warp_sum(float v) {
#pragma unroll
    for (int o = 16; o > 0; o >>= 1) v += __shfl_xor_sync(0xffffffffu, v, o);
    return v;
}

__device__ __forceinline__ float dot4(float4 a, float4 b) {
    return fmaf(a.x, b.x, fmaf(a.y, b.y, fmaf(a.z, b.z, a.w * b.w)));
}

// ---------------------------------------------------------------------------
// K1 (R5 winner, 13.2us) + merged alpha/la/ra epilogue (old K2).
// One BLOCK per 2 rows, 6 warps = (matrix, K-half):
//   mat 0 = Wh: streams rows j,j+1 over its K-half; dots with lh AND rh
//   mat 1 = Us: streams rows j,j+1; dots with S
//   mat 2 = ma: streams rows j,j+1; dots with lh AND rh
// Every matrix row read exactly once per block; vectors L1-resident.
// The LAST block to finish (threadfence-reduction pattern) computes the
// scalar alphas and writes la/ra — removing the separate K2 launch.
// ---------------------------------------------------------------------------
__global__ void __launch_bounds__(192) k1_score(
    const float* __restrict__ lh, const float* __restrict__ rh,
    const float* __restrict__ S,  const float* __restrict__ w,
    const float* __restrict__ Wh_w, const float* __restrict__ Wh_b,
    const float* __restrict__ Us_w, const float* __restrict__ Us_b,
    const float* __restrict__ ma_w, const float* __restrict__ ma_b)
{
    const int row0 = blockIdx.x * 2;
    const int wid  = threadIdx.x >> 5;   // 0..5
    const int lane = threadIdx.x & 31;
    const int mat  = wid >> 1;           // 0=Wh, 1=Us, 2=ma
    const int half = wid & 1;

    // s_res[row][slot][half]; slots: 0=WL 1=WR 2=US 3=ML 4=MR
    __shared__ float s_res[2][5][2];

    const float4* __restrict__ lh4 = (const float4*)lh;
    const float4* __restrict__ rh4 = (const float4*)rh;
    const int base = half * (NV4 / 2) + lane;

    if (mat == 1) {
        const float4* __restrict__ M0 = (const float4*)Us_w + (size_t)row0 * NV4;
        const float4* __restrict__ M1 = M0 + NV4;
        const float4* __restrict__ S4 = (const float4*)S;
        float a0 = 0.f, a1 = 0.f;
#pragma unroll 4
        for (int i = 0; i < 8; i++) {
            const int idx = base + i * 32;
            float4 s = S4[idx];
            a0 += dot4(M0[idx], s);
            a1 += dot4(M1[idx], s);
        }
        a0 = warp_sum(a0);
        a1 = warp_sum(a1);
        if (lane == 0) { s_res[0][2][half] = a0; s_res[1][2][half] = a1; }
    } else {
        const float* matp = (mat == 0) ? Wh_w : ma_w;
        const int slotL = (mat == 0) ? 0 : 3;
        const float4* __restrict__ M0 = (const float4*)matp + (size_t)row0 * NV4;
        const float4* __restrict__ M1 = M0 + NV4;
        float a0L = 0.f, a0R = 0.f, a1L = 0.f, a1R = 0.f;
#pragma unroll 4
        for (int i = 0; i < 8; i++) {
            const int idx = base + i * 32;
            float4 m0 = M0[idx];
            float4 m1 = M1[idx];
            float4 l  = lh4[idx];
            float4 r  = rh4[idx];
            a0L += dot4(m0, l);
            a0R += dot4(m0, r);
            a1L += dot4(m1, l);
            a1R += dot4(m1, r);
        }
        a0L = warp_sum(a0L);
        a0R = warp_sum(a0R);
        a1L = warp_sum(a1L);
        a1R = warp_sum(a1R);
        if (lane == 0) {
            s_res[0][slotL][half]     = a0L;
            s_res[0][slotL + 1][half] = a0R;
            s_res[1][slotL][half]     = a1L;
            s_res[1][slotL + 1][half] = a1R;
        }
    }
    __syncthreads();

    if (threadIdx.x < 2) {
        const int r = threadIdx.x;
        const int j = row0 + r;
        const float aWL = s_res[r][0][0] + s_res[r][0][1];
        const float aWR = s_res[r][1][0] + s_res[r][1][1];
        const float aUS = s_res[r][2][0] + s_res[r][2][1];
        const float base_b = Wh_b[j] + Us_b[j];
        const float mL = tanhf(aWL + aUS + base_b);
        const float mR = tanhf(aWR + aUS + base_b);
        const float wj = w[j];
        g_sL[j] = wj * mL;
        g_sR[j] = wj * mR;
        g_pL[j] = s_res[r][3][0] + s_res[r][3][1];
        g_pR[j] = s_res[r][4][0] + s_res[r][4][1];
    }

    // ---- merged K2: last block computes alphas and la/ra ----
    __threadfence();
    __syncthreads();
    __shared__ unsigned int s_last;
    if (threadIdx.x == 0)
        s_last = (atomicAdd(&g_count, 1u) == (unsigned)(gridDim.x - 1)) ? 1u : 0u;
    __syncthreads();
    if (s_last) {
        __threadfence();   // acquire: see all blocks' g_s*/g_p* writes
        __shared__ float rL[6], rR[6];
        __shared__ float s_aL, s_aR;
        float accL = 0.f, accR = 0.f;
        for (int j = threadIdx.x; j < MEM; j += 192) {
            accL += g_sL[j];
            accR += g_sR[j];
        }
        accL = warp_sum(accL);
        accR = warp_sum(accR);
        if (lane == 0) { rL[wid] = accL; rR[wid] = accR; }
        __syncthreads();
        if (threadIdx.x == 0) {
            const float eL = rL[0] + rL[1] + rL[2] + rL[3] + rL[4] + rL[5];
            const float eR = rR[0] + rR[1] + rR[2] + rR[3] + rR[4] + rR[5];
            const float inv = 1.0f / (eL + eR);
            s_aL = eL * inv;
            s_aR = eR * inv;
            g_count = 0;   // reset for next graph replay
        }
        __syncthreads();
        const float aL = s_aL, aR = s_aR;
        for (int j = threadIdx.x; j < MEM; j += 192) {
            const float b = ma_b[j];
            g_la[j] = tanhf(fmaf(aL, g_pL[j], b));
            g_ra[j] = tanhf(fmaf(aR, g_pR[j], b));
        }
    }
}

// ---------------------------------------------------------------------------
// K3 (R2 winner, 26.3us): all 8 gate matvecs + LSTM combine.
// One BLOCK per output element j, 8 warps: one warp per gate matrix.
// Even warps dot with la, odd warps dot with ra (L1-resident vectors).
// ---------------------------------------------------------------------------
__global__ void __launch_bounds__(256) k3_gates(
    const float* __restrict__ lc, const float* __restrict__ rc,
    const float* __restrict__ ilh_w,  const float* __restrict__ ilh_b,
    const float* __restrict__ irh_w,  const float* __restrict__ irh_b,
    const float* __restrict__ lflh_w, const float* __restrict__ lflh_b,
    const float* __restrict__ lfrh_w, const float* __restrict__ lfrh_b,
    const float* __restrict__ rflh_w, const float* __restrict__ rflh_b,
    const float* __restrict__ rfrh_w, const float* __restrict__ rfrh_b,
    const float* __restrict__ ulh_w,  const float* __restrict__ ulh_b,
    const float* __restrict__ urh_w,  const float* __restrict__ urh_b,
    float* __restrict__ out)
{
    const int row  = blockIdx.x;
    const int wid  = threadIdx.x >> 5;   // 0..7 = gate index
    const int lane = threadIdx.x & 31;

    __shared__ float s_g[8];

    const float* mat;
    switch (wid) {
        case 0: mat = ilh_w;  break;
        case 1: mat = irh_w;  break;
        case 2: mat = lflh_w; break;
        case 3: mat = lfrh_w; break;
        case 4: mat = rflh_w; break;
        case 5: mat = rfrh_w; break;
        case 6: mat = ulh_w;  break;
        default: mat = urh_w; break;
    }
    const float4* __restrict__ M = (const float4*)mat + (size_t)row * NV4;
    const float4* __restrict__ V = (wid & 1) ? (const float4*)g_ra
                                             : (const float4*)g_la;

    float acc = 0.f;
#pragma unroll 8
    for (int i = 0; i < 16; i++) {
        const int idx = i * 32 + lane;
        acc += dot4(M[idx], V[idx]);
    }
    acc = warp_sum(acc);
    if (lane == 0) s_g[wid] = acc;
    __syncthreads();

    if (threadIdx.x == 0) {
        const int j = row;
        const float gi  = s_g[0] + s_g[1] + ilh_b[j]  + irh_b[j];
        const float glf = s_g[2] + s_g[3] + lflh_b[j] + lfrh_b[j];
        const float grf = s_g[4] + s_g[5] + rflh_b[j] + rfrh_b[j];
        const float gu  = s_g[6] + s_g[7] + ulh_b[j]  + urh_b[j];
        const float ig  = 1.0f / (1.0f + expf(-gi));
        const float lf  = 1.0f / (1.0f + expf(-glf));
        const float rf  = 1.0f / (1.0f + expf(-grf));
        const float u   = tanhf(gu);
        const float c   = ig * u + lf * lc[j] + rf * rc[j];
        out[j]       = c;
        out[MEM + j] = tanhf(c);
    }
}

// ---------------------------------------------------------------------------
// Input order (metadata): lc, lh, rc, rh, S, w, then (W, b) pairs for
// Wh, Us, ma, ilh, irh, lflh, lfrh, rflh, rfrh, ulh, urh.
// Output: c (2048 floats) followed by h (2048 floats).
// ---------------------------------------------------------------------------
extern "C" void kernel_launch(void* const* d_in, const int* in_sizes, int n_in,
                              void* d_out, int out_size)
{
    const float* lc = (const float*)d_in[0];
    const float* lh = (const float*)d_in[1];
    const float* rc = (const float*)d_in[2];
    const float* rh = (const float*)d_in[3];
    const float* S  = (const float*)d_in[4];
    const float* w  = (const float*)d_in[5];

    const float* Wh_w   = (const float*)d_in[6];
    const float* Wh_b   = (const float*)d_in[7];
    const float* Us_w   = (const float*)d_in[8];
    const float* Us_b   = (const float*)d_in[9];
    const float* ma_w   = (const float*)d_in[10];
    const float* ma_b   = (const float*)d_in[11];
    const float* ilh_w  = (const float*)d_in[12];
    const float* ilh_b  = (const float*)d_in[13];
    const float* irh_w  = (const float*)d_in[14];
    const float* irh_b  = (const float*)d_in[15];
    const float* lflh_w = (const float*)d_in[16];
    const float* lflh_b = (const float*)d_in[17];
    const float* lfrh_w = (const float*)d_in[18];
    const float* lfrh_b = (const float*)d_in[19];
    const float* rflh_w = (const float*)d_in[20];
    const float* rflh_b = (const float*)d_in[21];
    const float* rfrh_w = (const float*)d_in[22];
    const float* rfrh_b = (const float*)d_in[23];
    const float* ulh_w  = (const float*)d_in[24];
    const float* ulh_b  = (const float*)d_in[25];
    const float* urh_w  = (const float*)d_in[26];
    const float* urh_b  = (const float*)d_in[27];

    float* out = (float*)d_out;

    k1_score<<<MEM / 2, 192>>>(lh, rh, S, w, Wh_w, Wh_b, Us_w, Us_b,
                               ma_w, ma_b);
    k3_gates<<<MEM, 256>>>(lc, rc,
                           ilh_w, ilh_b, irh_w, irh_b,
                           lflh_w, lflh_b, lfrh_w, lfrh_b,
                           rflh_w, rflh_b, rfrh_w, rfrh_b,
                           ulh_w, ulh_b, urh_w, urh_b,
                           out);
}

// round 11
// speedup vs baseline: 1.2393x; 1.2393x over previous
#include <cuda_runtime.h>
#include <math.h>

#define MEM 2048
#define NV4 (MEM / 4)          // float4 per row = 512

// Scratch (allocation-free: __device__ globals)
__device__ float g_sL[MEM];    // w[j] * m_left[j]
__device__ float g_sR[MEM];    // w[j] * m_right[j]
__device__ float g_pL[MEM];    // (ma @ lh)[j]
__device__ float g_pR[MEM];    // (ma @ rh)[j]
__device__ float g_la[MEM];
__device__ float g_ra[MEM];

__device__ __forceinline__ float warp_sum(float v) {
#pragma unroll
    for (int o = 16; o > 0; o >>= 1) v += __shfl_xor_sync(0xffffffffu, v, o);
    return v;
}

__device__ __forceinline__ float dot4(float4 a, float4 b) {
    return fmaf(a.x, b.x, fmaf(a.y, b.y, fmaf(a.z, b.z, a.w * b.w)));
}

// ---------------------------------------------------------------------------
// K1 (R5 winner, 13.2us, reproduced 3x): One BLOCK per 2 rows, 6 warps =
// (matrix, K-half):
//   mat 0 = Wh: streams rows j,j+1 over its K-half; dots with lh AND rh
//   mat 1 = Us: streams rows j,j+1; dots with S
//   mat 2 = ma: streams rows j,j+1; dots with lh AND rh
// Every matrix row read exactly once per block; vectors L1-resident.
// ---------------------------------------------------------------------------
__global__ void __launch_bounds__(192) k1_score(
    const float* __restrict__ lh, const float* __restrict__ rh,
    const float* __restrict__ S,  const float* __restrict__ w,
    const float* __restrict__ Wh_w, const float* __restrict__ Wh_b,
    const float* __restrict__ Us_w, const float* __restrict__ Us_b,
    const float* __restrict__ ma_w)
{
    const int row0 = blockIdx.x * 2;
    const int wid  = threadIdx.x >> 5;   // 0..5
    const int lane = threadIdx.x & 31;
    const int mat  = wid >> 1;           // 0=Wh, 1=Us, 2=ma
    const int half = wid & 1;

    // s_res[row][slot][half]; slots: 0=WL 1=WR 2=US 3=ML 4=MR
    __shared__ float s_res[2][5][2];

    const float4* __restrict__ lh4 = (const float4*)lh;
    const float4* __restrict__ rh4 = (const float4*)rh;
    const int base = half * (NV4 / 2) + lane;

    if (mat == 1) {
        const float4* __restrict__ M0 = (const float4*)Us_w + (size_t)row0 * NV4;
        const float4* __restrict__ M1 = M0 + NV4;
        const float4* __restrict__ S4 = (const float4*)S;
        float a0 = 0.f, a1 = 0.f;
#pragma unroll 4
        for (int i = 0; i < 8; i++) {
            const int idx = base + i * 32;
            float4 s = S4[idx];
            a0 += dot4(M0[idx], s);
            a1 += dot4(M1[idx], s);
        }
        a0 = warp_sum(a0);
        a1 = warp_sum(a1);
        if (lane == 0) { s_res[0][2][half] = a0; s_res[1][2][half] = a1; }
    } else {
        const float* matp = (mat == 0) ? Wh_w : ma_w;
        const int slotL = (mat == 0) ? 0 : 3;
        const float4* __restrict__ M0 = (const float4*)matp + (size_t)row0 * NV4;
        const float4* __restrict__ M1 = M0 + NV4;
        float a0L = 0.f, a0R = 0.f, a1L = 0.f, a1R = 0.f;
#pragma unroll 4
        for (int i = 0; i < 8; i++) {
            const int idx = base + i * 32;
            float4 m0 = M0[idx];
            float4 m1 = M1[idx];
            float4 l  = lh4[idx];
            float4 r  = rh4[idx];
            a0L += dot4(m0, l);
            a0R += dot4(m0, r);
            a1L += dot4(m1, l);
            a1R += dot4(m1, r);
        }
        a0L = warp_sum(a0L);
        a0R = warp_sum(a0R);
        a1L = warp_sum(a1L);
        a1R = warp_sum(a1R);
        if (lane == 0) {
            s_res[0][slotL][half]     = a0L;
            s_res[0][slotL + 1][half] = a0R;
            s_res[1][slotL][half]     = a1L;
            s_res[1][slotL + 1][half] = a1R;
        }
    }
    __syncthreads();

    if (threadIdx.x < 2) {
        const int r = threadIdx.x;
        const int j = row0 + r;
        const float aWL = s_res[r][0][0] + s_res[r][0][1];
        const float aWR = s_res[r][1][0] + s_res[r][1][1];
        const float aUS = s_res[r][2][0] + s_res[r][2][1];
        const float base_b = Wh_b[j] + Us_b[j];
        const float mL = tanhf(aWL + aUS + base_b);
        const float mR = tanhf(aWR + aUS + base_b);
        const float wj = w[j];
        g_sL[j] = wj * mL;
        g_sR[j] = wj * mR;
        g_pL[j] = s_res[r][3][0] + s_res[r][3][1];
        g_pR[j] = s_res[r][4][0] + s_res[r][4][1];
    }
}

// ---------------------------------------------------------------------------
// K2: reduce scores -> alphas -> la/ra. Single block (tiny, ~2.1us).
// ---------------------------------------------------------------------------
__global__ void __launch_bounds__(1024) k2_alpha(const float* __restrict__ ma_b)
{
    __shared__ float sL[1024];
    __shared__ float sR[1024];
    __shared__ float s_aL, s_aR;
    const int t = threadIdx.x;

    sL[t] = g_sL[t] + g_sL[t + 1024];
    sR[t] = g_sR[t] + g_sR[t + 1024];
    __syncthreads();
#pragma unroll
    for (int s = 512; s > 0; s >>= 1) {
        if (t < s) { sL[t] += sL[t + s]; sR[t] += sR[t + s]; }
        __syncthreads();
    }
    if (t == 0) {
        const float eL = sL[0], eR = sR[0];
        const float inv = 1.0f / (eL + eR);
        s_aL = eL * inv;
        s_aR = eR * inv;
    }
    __syncthreads();
    const float aL = s_aL, aR = s_aR;

#pragma unroll
    for (int j = t; j < MEM; j += 1024) {
        const float b = ma_b[j];
        g_la[j] = tanhf(fmaf(aL, g_pL[j], b));
        g_ra[j] = tanhf(fmaf(aR, g_pR[j], b));
    }
}

// ---------------------------------------------------------------------------
// K3 (R2 winner, 26.3us, reproduced 3x): all 8 gate matvecs + LSTM combine.
// One BLOCK per output element j, 8 warps: one warp per gate matrix.
// Even warps dot with la, odd warps dot with ra (L1-resident vectors).
// ---------------------------------------------------------------------------
__global__ void __launch_bounds__(256) k3_gates(
    const float* __restrict__ lc, const float* __restrict__ rc,
    const float* __restrict__ ilh_w,  const float* __restrict__ ilh_b,
    const float* __restrict__ irh_w,  const float* __restrict__ irh_b,
    const float* __restrict__ lflh_w, const float* __restrict__ lflh_b,
    const float* __restrict__ lfrh_w, const float* __restrict__ lfrh_b,
    const float* __restrict__ rflh_w, const float* __restrict__ rflh_b,
    const float* __restrict__ rfrh_w, const float* __restrict__ rfrh_b,
    const float* __restrict__ ulh_w,  const float* __restrict__ ulh_b,
    const float* __restrict__ urh_w,  const float* __restrict__ urh_b,
    float* __restrict__ out)
{
    const int row  = blockIdx.x;
    const int wid  = threadIdx.x >> 5;   // 0..7 = gate index
    const int lane = threadIdx.x & 31;

    __shared__ float s_g[8];

    const float* mat;
    switch (wid) {
        case 0: mat = ilh_w;  break;
        case 1: mat = irh_w;  break;
        case 2: mat = lflh_w; break;
        case 3: mat = lfrh_w; break;
        case 4: mat = rflh_w; break;
        case 5: mat = rfrh_w; break;
        case 6: mat = ulh_w;  break;
        default: mat = urh_w; break;
    }
    const float4* __restrict__ M = (const float4*)mat + (size_t)row * NV4;
    const float4* __restrict__ V = (wid & 1) ? (const float4*)g_ra
                                             : (const float4*)g_la;

    float acc = 0.f;
#pragma unroll 8
    for (int i = 0; i < 16; i++) {
        const int idx = i * 32 + lane;
        acc += dot4(M[idx], V[idx]);
    }
    acc = warp_sum(acc);
    if (lane == 0) s_g[wid] = acc;
    __syncthreads();

    if (threadIdx.x == 0) {
        const int j = row;
        const float gi  = s_g[0] + s_g[1] + ilh_b[j]  + irh_b[j];
        const float glf = s_g[2] + s_g[3] + lflh_b[j] + lfrh_b[j];
        const float grf = s_g[4] + s_g[5] + rflh_b[j] + rfrh_b[j];
        const float gu  = s_g[6] + s_g[7] + ulh_b[j]  + urh_b[j];
        const float ig  = 1.0f / (1.0f + expf(-gi));
        const float lf  = 1.0f / (1.0f + expf(-glf));
        const float rf  = 1.0f / (1.0f + expf(-grf));
        const float u   = tanhf(gu);
        const float c   = ig * u + lf * lc[j] + rf * rc[j];
        out[j]       = c;
        out[MEM + j] = tanhf(c);
    }
}

// ---------------------------------------------------------------------------
// Input order (metadata): lc, lh, rc, rh, S, w, then (W, b) pairs for
// Wh, Us, ma, ilh, irh, lflh, lfrh, rflh, rfrh, ulh, urh.
// Output: c (2048 floats) followed by h (2048 floats).
// ---------------------------------------------------------------------------
extern "C" void kernel_launch(void* const* d_in, const int* in_sizes, int n_in,
                              void* d_out, int out_size)
{
    const float* lc = (const float*)d_in[0];
    const float* lh = (const float*)d_in[1];
    const float* rc = (const float*)d_in[2];
    const float* rh = (const float*)d_in[3];
    const float* S  = (const float*)d_in[4];
    const float* w  = (const float*)d_in[5];

    const float* Wh_w   = (const float*)d_in[6];
    const float* Wh_b   = (const float*)d_in[7];
    const float* Us_w   = (const float*)d_in[8];
    const float* Us_b   = (const float*)d_in[9];
    const float* ma_w   = (const float*)d_in[10];
    const float* ma_b   = (const float*)d_in[11];
    const float* ilh_w  = (const float*)d_in[12];
    const float* ilh_b  = (const float*)d_in[13];
    const float* irh_w  = (const float*)d_in[14];
    const float* irh_b  = (const float*)d_in[15];
    const float* lflh_w = (const float*)d_in[16];
    const float* lflh_b = (const float*)d_in[17];
    const float* lfrh_w = (const float*)d_in[18];
    const float* lfrh_b = (const float*)d_in[19];
    const float* rflh_w = (const float*)d_in[20];
    const float* rflh_b = (const float*)d_in[21];
    const float* rfrh_w = (const float*)d_in[22];
    const float* rfrh_b = (const float*)d_in[23];
    const float* ulh_w  = (const float*)d_in[24];
    const float* ulh_b  = (const float*)d_in[25];
    const float* urh_w  = (const float*)d_in[26];
    const float* urh_b  = (const float*)d_in[27];

    float* out = (float*)d_out;

    k1_score<<<MEM / 2, 192>>>(lh, rh, S, w, Wh_w, Wh_b, Us_w, Us_b, ma_w);
    k2_alpha<<<1, 1024>>>(ma_b);
    k3_gates<<<MEM, 256>>>(lc, rc,
                           ilh_w, ilh_b, irh_w, irh_b,
                           lflh_w, lflh_b, lfrh_w, lfrh_b,
                           rflh_w, rflh_b, rfrh_w, rfrh_b,
                           ulh_w, ulh_b, urh_w, urh_b,
                           out);
}